// round 1
// baseline (speedup 1.0000x reference)
#include <cuda_runtime.h>
#include <cstdint>

#define T_SEQ 4096
#define D_MODEL 1024

// Scratch (allocation-free rule: __device__ globals)
__device__ float g_Q[T_SEQ * D_MODEL];
__device__ float g_K[T_SEQ * D_MODEL];

// ---------------- Threefry-2x32-20, JAX partitionable 32-bit path ----------
// key(123) -> (k1,k2) = (0,123); counts = (hi,lo) of 64-bit iota = (0, idx)
// bits = x0 ^ x1 after 20 rounds; keep = !(bits >> 31)
__device__ __forceinline__ uint32_t rotl32(uint32_t x, int r) {
    return (x << r) | (x >> (32 - r));
}

__device__ __forceinline__ uint32_t jax_random_bits(uint32_t idx) {
    const uint32_t ks0 = 0u;
    const uint32_t ks1 = 123u;
    const uint32_t ks2 = 0x1BD11BDAu ^ ks0 ^ ks1;
    uint32_t x0 = 0u + ks0;     // counts_hi = 0
    uint32_t x1 = idx + ks1;    // counts_lo = idx
#define TF_ROUND(r) { x0 += x1; x1 = rotl32(x1, (r)); x1 ^= x0; }
    TF_ROUND(13) TF_ROUND(15) TF_ROUND(26) TF_ROUND(6)
    x0 += ks1; x1 += ks2 + 1u;
    TF_ROUND(17) TF_ROUND(29) TF_ROUND(16) TF_ROUND(24)
    x0 += ks2; x1 += ks0 + 2u;
    TF_ROUND(13) TF_ROUND(15) TF_ROUND(26) TF_ROUND(6)
    x0 += ks0; x1 += ks1 + 3u;
    TF_ROUND(17) TF_ROUND(29) TF_ROUND(16) TF_ROUND(24)
    x0 += ks1; x1 += ks2 + 4u;
    TF_ROUND(13) TF_ROUND(15) TF_ROUND(26) TF_ROUND(6)
    x0 += ks2; x1 += ks0 + 5u;
#undef TF_ROUND
    return x0 ^ x1;
}

// ---------------- NT GEMM: C[M,N] = alpha * A[M,K] * B[N,K]^T --------------
// 128x128 tile, BK=8, 256 threads, 8x8 per thread.
// lowerOnly: skip tiles strictly above the block diagonal (bi < bj).
__global__ __launch_bounds__(256)
void gemm_nt_128(const float* __restrict__ A, const float* __restrict__ B,
                 float* __restrict__ C, int K, int ldc, float alpha, int lowerOnly)
{
    int bj = blockIdx.x, bi = blockIdx.y;
    if (lowerOnly && bi < bj) return;

    __shared__ float As[8][128];
    __shared__ float Bs[8][128];

    int tid = threadIdx.x;
    int lr = tid >> 1;          // 0..127 : row within tile to load
    int lc = (tid & 1) << 2;    // 0 or 4 : k-offset of float4
    const float* Aptr = A + (size_t)(bi * 128 + lr) * K + lc;
    const float* Bptr = B + (size_t)(bj * 128 + lr) * K + lc;

    int tx = tid & 15;          // 0..15 -> 8 columns each
    int ty = tid >> 4;          // 0..15 -> 8 rows each

    float acc[8][8];
#pragma unroll
    for (int i = 0; i < 8; i++)
#pragma unroll
        for (int j = 0; j < 8; j++) acc[i][j] = 0.f;

    for (int k0 = 0; k0 < K; k0 += 8) {
        float4 a4 = *(const float4*)(Aptr + k0);
        float4 b4 = *(const float4*)(Bptr + k0);
        __syncthreads();   // previous iteration's consumers done
        As[lc + 0][lr] = a4.x; As[lc + 1][lr] = a4.y;
        As[lc + 2][lr] = a4.z; As[lc + 3][lr] = a4.w;
        Bs[lc + 0][lr] = b4.x; Bs[lc + 1][lr] = b4.y;
        Bs[lc + 2][lr] = b4.z; Bs[lc + 3][lr] = b4.w;
        __syncthreads();
#pragma unroll
        for (int kk = 0; kk < 8; kk++) {
            float a[8], b[8];
            *(float4*)(a)     = *(const float4*)&As[kk][ty * 8];
            *(float4*)(a + 4) = *(const float4*)&As[kk][ty * 8 + 4];
            *(float4*)(b)     = *(const float4*)&Bs[kk][tx * 8];
            *(float4*)(b + 4) = *(const float4*)&Bs[kk][tx * 8 + 4];
#pragma unroll
            for (int i = 0; i < 8; i++)
#pragma unroll
                for (int j = 0; j < 8; j++) acc[i][j] += a[i] * b[j];
        }
    }

#pragma unroll
    for (int i = 0; i < 8; i++) {
        size_t row = (size_t)(bi * 128 + ty * 8 + i);
        float* Cp = C + row * ldc + (bj * 128 + tx * 8);
        float4 o0, o1;
        o0.x = acc[i][0] * alpha; o0.y = acc[i][1] * alpha;
        o0.z = acc[i][2] * alpha; o0.w = acc[i][3] * alpha;
        o1.x = acc[i][4] * alpha; o1.y = acc[i][5] * alpha;
        o1.z = acc[i][6] * alpha; o1.w = acc[i][7] * alpha;
        *(float4*)(Cp)     = o0;
        *(float4*)(Cp + 4) = o1;
    }
}

// ------------- Causal softmax + dropout (in place over d_out) --------------
// One block per row. Row held in registers (16 elems/thread).
__global__ __launch_bounds__(256)
void softmax_dropout_kernel(float* __restrict__ buf)
{
    int row = blockIdx.x;
    int tid = threadIdx.x;
    int len = row + 1;                       // causal: valid j in [0, len)
    float* rp = buf + (size_t)row * T_SEQ;

    float v[16];
    float mx = -3.0e38f;
#pragma unroll
    for (int t = 0; t < 16; t++) {
        int j = tid + (t << 8);
        v[t] = (j < len) ? rp[j] : -3.0e38f;
        mx = fmaxf(mx, v[t]);
    }

    __shared__ float sred[8];
#pragma unroll
    for (int o = 16; o > 0; o >>= 1)
        mx = fmaxf(mx, __shfl_xor_sync(0xffffffffu, mx, o));
    if ((tid & 31) == 0) sred[tid >> 5] = mx;
    __syncthreads();
    mx = sred[0];
#pragma unroll
    for (int w = 1; w < 8; w++) mx = fmaxf(mx, sred[w]);

    float sum = 0.f;
#pragma unroll
    for (int t = 0; t < 16; t++) {
        int j = tid + (t << 8);
        if (j < len) { v[t] = __expf(v[t] - mx); sum += v[t]; }
    }
#pragma unroll
    for (int o = 16; o > 0; o >>= 1)
        sum += __shfl_xor_sync(0xffffffffu, sum, o);
    __syncthreads();
    if ((tid & 31) == 0) sred[tid >> 5] = sum;
    __syncthreads();
    sum = 0.f;
#pragma unroll
    for (int w = 0; w < 8; w++) sum += sred[w];

    float inv = 2.0f / sum;                  // includes /(1-p) with p=0.5
    uint32_t base = (uint32_t)row * (uint32_t)T_SEQ + (uint32_t)tid;
#pragma unroll
    for (int t = 0; t < 16; t++) {
        int j = tid + (t << 8);
        float o = 0.f;
        if (j < len) {
            uint32_t bits = jax_random_bits(base + ((uint32_t)t << 8));
            if (!(bits & 0x80000000u)) o = v[t] * inv;
        }
        rp[j] = o;                           // also zeros j > row (poisoned out)
    }
}

// ---------------------------------------------------------------------------
extern "C" void kernel_launch(void* const* d_in, const int* in_sizes, int n_in,
                              void* d_out, int out_size)
{
    const float* x  = (const float*)d_in[0];
    const float* Wq = (const float*)d_in[1];
    const float* Wk = (const float*)d_in[2];
    // d_in[3] = W_value: dead code in the reference, unused.
    float* out = (float*)d_out;

    float *Qp = nullptr, *Kp = nullptr;
    cudaGetSymbolAddress((void**)&Qp, g_Q);
    cudaGetSymbolAddress((void**)&Kp, g_K);

    dim3 blk(256);
    // Q = x @ Wq^T  and  K = x @ Wk^T   [4096,1024] x [1024,1024]^T
    gemm_nt_128<<<dim3(D_MODEL / 128, T_SEQ / 128), blk>>>(x, Wq, Qp, D_MODEL, D_MODEL, 1.0f, 0);
    gemm_nt_128<<<dim3(D_MODEL / 128, T_SEQ / 128), blk>>>(x, Wk, Kp, D_MODEL, D_MODEL, 1.0f, 0);
    // S = Q @ K^T / sqrt(d)  -- lower-triangular tiles only
    gemm_nt_128<<<dim3(T_SEQ / 128, T_SEQ / 128), blk>>>(Qp, Kp, out, D_MODEL, T_SEQ, 0.03125f, 1);
    // causal softmax + threefry dropout, in place
    softmax_dropout_kernel<<<T_SEQ, 256>>>(out);
}

// round 3
// speedup vs baseline: 2.4114x; 2.4114x over previous
#include <cuda_runtime.h>
#include <cuda_bf16.h>
#include <cstdint>

#define T_SEQ 4096
#define D_MODEL 1024

// ---------------- scratch (__device__ globals; no allocs allowed) ----------
__device__ __nv_bfloat16 g_xh[T_SEQ * D_MODEL];
__device__ __nv_bfloat16 g_xl[T_SEQ * D_MODEL];
__device__ __nv_bfloat16 g_Wqh[D_MODEL * D_MODEL];
__device__ __nv_bfloat16 g_Wql[D_MODEL * D_MODEL];
__device__ __nv_bfloat16 g_Wkh[D_MODEL * D_MODEL];
__device__ __nv_bfloat16 g_Wkl[D_MODEL * D_MODEL];
__device__ __nv_bfloat16 g_Qh[T_SEQ * D_MODEL];
__device__ __nv_bfloat16 g_Ql[T_SEQ * D_MODEL];
__device__ __nv_bfloat16 g_Kh[T_SEQ * D_MODEL];
__device__ __nv_bfloat16 g_Kl[T_SEQ * D_MODEL];

// ---------------- helpers ---------------------------------------------------
__device__ __forceinline__ uint32_t smem_u32(const void* p) {
    uint32_t a;
    asm("{ .reg .u64 t; cvta.to.shared.u64 t, %1; cvt.u32.u64 %0, t; }" : "=r"(a) : "l"(p));
    return a;
}
__device__ __forceinline__ void cp_async16(uint32_t s, const void* g) {
    asm volatile("cp.async.cg.shared.global [%0], [%1], 16;" :: "r"(s), "l"(g));
}
__device__ __forceinline__ void cp_commit() {
    asm volatile("cp.async.commit_group;" ::: "memory");
}
template <int N> __device__ __forceinline__ void cp_wait() {
    asm volatile("cp.async.wait_group %0;" :: "n"(N) : "memory");
}
__device__ __forceinline__ void ldsm4(uint32_t* r, uint32_t addr) {
    asm volatile("ldmatrix.sync.aligned.m8n8.x4.shared.b16 {%0,%1,%2,%3}, [%4];"
                 : "=r"(r[0]), "=r"(r[1]), "=r"(r[2]), "=r"(r[3]) : "r"(addr));
}
__device__ __forceinline__ void mma16816(float* c, const uint32_t* a, uint32_t b0, uint32_t b1) {
    asm volatile(
        "mma.sync.aligned.m16n8k16.row.col.f32.bf16.bf16.f32 "
        "{%0,%1,%2,%3}, {%4,%5,%6,%7}, {%8,%9}, {%0,%1,%2,%3};"
        : "+f"(c[0]), "+f"(c[1]), "+f"(c[2]), "+f"(c[3])
        : "r"(a[0]), "r"(a[1]), "r"(a[2]), "r"(a[3]), "r"(b0), "r"(b1));
}

// ---------------- fp32 -> bf16 hi/lo conversion ----------------------------
__global__ void convert_hilo(const float* __restrict__ s, __nv_bfloat16* __restrict__ hi,
                             __nv_bfloat16* __restrict__ lo, int n)
{
    int i = (blockIdx.x * blockDim.x + threadIdx.x) * 2;
    if (i < n) {
        float2 v = *(const float2*)(s + i);
        __nv_bfloat16 h0 = __float2bfloat16(v.x);
        __nv_bfloat16 h1 = __float2bfloat16(v.y);
        __nv_bfloat16 l0 = __float2bfloat16(v.x - __bfloat162float(h0));
        __nv_bfloat16 l1 = __float2bfloat16(v.y - __bfloat162float(h1));
        *(__nv_bfloat162*)(hi + i) = __halves2bfloat162(h0, h1);
        *(__nv_bfloat162*)(lo + i) = __halves2bfloat162(l0, l1);
    }
}

// ---------------- HMMA bf16x3 NT GEMM --------------------------------------
// C[M,N] = alpha * A[M,K] * B[N,K]^T, A/B given as bf16 (hi,lo) pairs.
// Block tile 128x64, BK=32, 256 threads (8 warps, warp tile 32x32).
// Output fp32 (Cf) or bf16 hi/lo (Ch, Cl).
__global__ __launch_bounds__(256, 2)
void gemm_mma_bf16x3(const __nv_bfloat16* __restrict__ Ah, const __nv_bfloat16* __restrict__ Al,
                     const __nv_bfloat16* __restrict__ Bh, const __nv_bfloat16* __restrict__ Bl,
                     int K, float* __restrict__ Cf,
                     __nv_bfloat16* __restrict__ Ch, __nv_bfloat16* __restrict__ Cl,
                     int ldc, float alpha, int lowerOnly)
{
    const int bj = blockIdx.x, bi = blockIdx.y;
    if (lowerOnly && bj > 2 * bi + 1) return;

    // [buf][hi/lo][row*4 + swizzled 16B chunk]
    __shared__ uint4 sA[2][2][512];   // 128 rows x 32 bf16
    __shared__ uint4 sB[2][2][256];   //  64 rows x 32 bf16

    const int tid = threadIdx.x;
    const uint32_t aBase = smem_u32(sA);
    const uint32_t bBase = smem_u32(sB);

    // ---- load-thread mapping (swizzle: chunk ^= (row>>1)&3) ----
    int ar[2], aoff[2];
    size_t agoff[2];
    #pragma unroll
    for (int i = 0; i < 2; i++) {
        int idx = tid + i * 256;        // 0..511
        int r = idx >> 2, c = idx & 3;
        ar[i] = r;
        aoff[i] = (r * 4 + (c ^ ((r >> 1) & 3))) * 16;
        agoff[i] = (size_t)r * K + c * 8;
    }
    const int br = tid >> 2, bc = tid & 3;
    const int boff = (br * 4 + (bc ^ ((br >> 1) & 3))) * 16;
    const size_t bgoff = (size_t)br * K + bc * 8;

    const __nv_bfloat16* pAh = Ah + (size_t)(bi * 128) * K;
    const __nv_bfloat16* pAl = Al + (size_t)(bi * 128) * K;
    const __nv_bfloat16* pBh = Bh + (size_t)(bj * 64) * K;
    const __nv_bfloat16* pBl = Bl + (size_t)(bj * 64) * K;

    const int lane = tid & 31, wid = tid >> 5;
    const int wm = wid & 3, wn = wid >> 2;     // 4 x 2 warp grid
    const int lr = lane & 15, lg = lane >> 4;

    float c[2][4][4];
    #pragma unroll
    for (int i = 0; i < 2; i++)
        #pragma unroll
        for (int j = 0; j < 4; j++)
            #pragma unroll
            for (int q = 0; q < 4; q++) c[i][j][q] = 0.f;

    const int NIT = K >> 5;

    // prologue: iter 0 into buf 0
    #pragma unroll
    for (int i = 0; i < 2; i++) {
        cp_async16(aBase + 0 * 8192 + aoff[i], pAh + agoff[i]);
        cp_async16(aBase + 1 * 8192 + aoff[i], pAl + agoff[i]);
    }
    cp_async16(bBase + 0 * 4096 + boff, pBh + bgoff);
    cp_async16(bBase + 1 * 4096 + boff, pBl + bgoff);
    cp_commit();

    for (int it = 0; it < NIT; ++it) {
        const int buf = it & 1;
        if (it + 1 < NIT) {
            const int nb = buf ^ 1;
            const int k0 = (it + 1) << 5;
            #pragma unroll
            for (int i = 0; i < 2; i++) {
                cp_async16(aBase + (nb * 2 + 0) * 8192 + aoff[i], pAh + k0 + agoff[i]);
                cp_async16(aBase + (nb * 2 + 1) * 8192 + aoff[i], pAl + k0 + agoff[i]);
            }
            cp_async16(bBase + (nb * 2 + 0) * 4096 + boff, pBh + k0 + bgoff);
            cp_async16(bBase + (nb * 2 + 1) * 4096 + boff, pBl + k0 + bgoff);
            cp_commit();
            cp_wait<1>();
        } else {
            cp_wait<0>();
        }
        __syncthreads();

        #pragma unroll
        for (int s = 0; s < 2; ++s) {
            uint32_t ah[2][4], al[2][4], bh[2][4], bl[2][4];
            #pragma unroll
            for (int mi = 0; mi < 2; mi++) {
                int r = wm * 32 + mi * 16 + lr;
                uint32_t off = r * 64 + (((2 * s + lg) ^ ((r >> 1) & 3)) * 16);
                ldsm4(ah[mi], aBase + (buf * 2 + 0) * 8192 + off);
                ldsm4(al[mi], aBase + (buf * 2 + 1) * 8192 + off);
            }
            #pragma unroll
            for (int ni = 0; ni < 2; ni++) {
                int r = wn * 32 + ni * 16 + lr;
                uint32_t off = r * 64 + (((2 * s + lg) ^ ((r >> 1) & 3)) * 16);
                ldsm4(bh[ni], bBase + (buf * 2 + 0) * 4096 + off);
                ldsm4(bl[ni], bBase + (buf * 2 + 1) * 4096 + off);
            }
            #pragma unroll
            for (int mi = 0; mi < 2; mi++)
                #pragma unroll
                for (int ni = 0; ni < 2; ni++)
                    #pragma unroll
                    for (int h = 0; h < 2; h++) {
                        float* cc = c[mi][ni * 2 + h];
                        mma16816(cc, ah[mi], bh[ni][h], bh[ni][h + 2]);
                        mma16816(cc, ah[mi], bl[ni][h], bl[ni][h + 2]);
                        mma16816(cc, al[mi], bh[ni][h], bh[ni][h + 2]);
                    }
        }
        __syncthreads();
    }

    // ---- epilogue ----
    const int gq = lane >> 2, tig = lane & 3;
    #pragma unroll
    for (int mi = 0; mi < 2; mi++) {
        #pragma unroll
        for (int n8 = 0; n8 < 4; n8++) {
            int row0 = bi * 128 + wm * 32 + mi * 16 + gq;
            int col  = bj * 64 + wn * 32 + n8 * 8 + tig * 2;
            float* cc = c[mi][n8];
            if (Cf) {
                float2 v0, v1;
                v0.x = cc[0] * alpha; v0.y = cc[1] * alpha;
                v1.x = cc[2] * alpha; v1.y = cc[3] * alpha;
                *(float2*)(Cf + (size_t)row0 * ldc + col) = v0;
                *(float2*)(Cf + (size_t)(row0 + 8) * ldc + col) = v1;
            } else {
                #pragma unroll
                for (int hrow = 0; hrow < 2; hrow++) {
                    float v0 = cc[hrow * 2], v1 = cc[hrow * 2 + 1];
                    __nv_bfloat16 h0 = __float2bfloat16(v0);
                    __nv_bfloat16 h1 = __float2bfloat16(v1);
                    __nv_bfloat16 l0 = __float2bfloat16(v0 - __bfloat162float(h0));
                    __nv_bfloat16 l1 = __float2bfloat16(v1 - __bfloat162float(h1));
                    __nv_bfloat162 hh = __halves2bfloat162(h0, h1);
                    __nv_bfloat162 ll = __halves2bfloat162(l0, l1);
                    size_t o = (size_t)(row0 + hrow * 8) * ldc + col;
                    *(__nv_bfloat162*)(Ch + o) = hh;
                    *(__nv_bfloat162*)(Cl + o) = ll;
                }
            }
        }
    }
}

// ---------------- Threefry-2x32-20 (JAX partitionable path) ----------------
__device__ __forceinline__ uint32_t rotl32(uint32_t x, int r) {
    return (x << r) | (x >> (32 - r));
}
__device__ __forceinline__ uint32_t jax_random_bits(uint32_t idx) {
    const uint32_t ks0 = 0u;
    const uint32_t ks1 = 123u;
    const uint32_t ks2 = 0x1BD11BDAu ^ ks0 ^ ks1;
    uint32_t x0 = 0u + ks0;
    uint32_t x1 = idx + ks1;
#define TF_ROUND(r) { x0 += x1; x1 = rotl32(x1, (r)); x1 ^= x0; }
    TF_ROUND(13) TF_ROUND(15) TF_ROUND(26) TF_ROUND(6)
    x0 += ks1; x1 += ks2 + 1u;
    TF_ROUND(17) TF_ROUND(29) TF_ROUND(16) TF_ROUND(24)
    x0 += ks2; x1 += ks0 + 2u;
    TF_ROUND(13) TF_ROUND(15) TF_ROUND(26) TF_ROUND(6)
    x0 += ks0; x1 += ks1 + 3u;
    TF_ROUND(17) TF_ROUND(29) TF_ROUND(16) TF_ROUND(24)
    x0 += ks1; x1 += ks2 + 4u;
    TF_ROUND(13) TF_ROUND(15) TF_ROUND(26) TF_ROUND(6)
    x0 += ks2; x1 += ks0 + 5u;
#undef TF_ROUND
    return x0 ^ x1;
}

// ------------- Causal softmax + dropout (in place over d_out) --------------
__global__ __launch_bounds__(256)
void softmax_dropout_kernel(float* __restrict__ buf)
{
    int row = blockIdx.x;
    int tid = threadIdx.x;
    int len = row + 1;
    float* rp = buf + (size_t)row * T_SEQ;

    float v[16];
    float mx = -3.0e38f;
#pragma unroll
    for (int t = 0; t < 16; t++) {
        int j = tid + (t << 8);
        v[t] = (j < len) ? rp[j] : -3.0e38f;
        mx = fmaxf(mx, v[t]);
    }

    __shared__ float sred[8];
#pragma unroll
    for (int o = 16; o > 0; o >>= 1)
        mx = fmaxf(mx, __shfl_xor_sync(0xffffffffu, mx, o));
    if ((tid & 31) == 0) sred[tid >> 5] = mx;
    __syncthreads();
    mx = sred[0];
#pragma unroll
    for (int w = 1; w < 8; w++) mx = fmaxf(mx, sred[w]);

    float sum = 0.f;
#pragma unroll
    for (int t = 0; t < 16; t++) {
        int j = tid + (t << 8);
        if (j < len) { v[t] = __expf(v[t] - mx); sum += v[t]; }
    }
#pragma unroll
    for (int o = 16; o > 0; o >>= 1)
        sum += __shfl_xor_sync(0xffffffffu, sum, o);
    __syncthreads();
    if ((tid & 31) == 0) sred[tid >> 5] = sum;
    __syncthreads();
    sum = 0.f;
#pragma unroll
    for (int w = 0; w < 8; w++) sum += sred[w];

    float inv = 2.0f / sum;                  // includes /(1-p), p=0.5
    uint32_t base = (uint32_t)row * (uint32_t)T_SEQ + (uint32_t)tid;
#pragma unroll
    for (int t = 0; t < 16; t++) {
        int j = tid + (t << 8);
        float o = 0.f;
        if (j < len) {
            uint32_t bits = jax_random_bits(base + ((uint32_t)t << 8));
            if (!(bits & 0x80000000u)) o = v[t] * inv;
        }
        rp[j] = o;
    }
}

// ---------------------------------------------------------------------------
extern "C" void kernel_launch(void* const* d_in, const int* in_sizes, int n_in,
                              void* d_out, int out_size)
{
    const float* x  = (const float*)d_in[0];
    const float* Wq = (const float*)d_in[1];
    const float* Wk = (const float*)d_in[2];
    float* out = (float*)d_out;

    __nv_bfloat16 *xh, *xl, *wqh, *wql, *wkh, *wkl, *qh, *ql, *kh, *kl;
    cudaGetSymbolAddress((void**)&xh,  g_xh);
    cudaGetSymbolAddress((void**)&xl,  g_xl);
    cudaGetSymbolAddress((void**)&wqh, g_Wqh);
    cudaGetSymbolAddress((void**)&wql, g_Wql);
    cudaGetSymbolAddress((void**)&wkh, g_Wkh);
    cudaGetSymbolAddress((void**)&wkl, g_Wkl);
    cudaGetSymbolAddress((void**)&qh,  g_Qh);
    cudaGetSymbolAddress((void**)&ql,  g_Ql);
    cudaGetSymbolAddress((void**)&kh,  g_Kh);
    cudaGetSymbolAddress((void**)&kl,  g_Kl);

    int n1 = T_SEQ * D_MODEL, n2 = D_MODEL * D_MODEL;
    convert_hilo<<<(n1 / 2 + 255) / 256, 256>>>(x,  xh,  xl,  n1);
    convert_hilo<<<(n2 / 2 + 255) / 256, 256>>>(Wq, wqh, wql, n2);
    convert_hilo<<<(n2 / 2 + 255) / 256, 256>>>(Wk, wkh, wkl, n2);

    // Q = x @ Wq^T, K = x @ Wk^T  (outputs as bf16 hi/lo)
    gemm_mma_bf16x3<<<dim3(D_MODEL / 64, T_SEQ / 128), 256>>>(
        xh, xl, wqh, wql, D_MODEL, nullptr, qh, ql, D_MODEL, 1.0f, 0);
    gemm_mma_bf16x3<<<dim3(D_MODEL / 64, T_SEQ / 128), 256>>>(
        xh, xl, wkh, wkl, D_MODEL, nullptr, kh, kl, D_MODEL, 1.0f, 0);
    // S = Q @ K^T / 32  (lower-triangular tiles only, fp32 to d_out)
    gemm_mma_bf16x3<<<dim3(T_SEQ / 64, T_SEQ / 128), 256>>>(
        qh, ql, kh, kl, D_MODEL, out, nullptr, nullptr, T_SEQ, 0.03125f, 1);

    softmax_dropout_kernel<<<T_SEQ, 256>>>(out);
}

// round 4
// speedup vs baseline: 2.6168x; 1.0852x over previous
#include <cuda_runtime.h>
#include <cuda_bf16.h>
#include <cstdint>

#define T_SEQ 4096
#define D_MODEL 1024

// ---------------- scratch (__device__ globals; no allocs allowed) ----------
__device__ __nv_bfloat16 g_xh[T_SEQ * D_MODEL];
__device__ __nv_bfloat16 g_xl[T_SEQ * D_MODEL];
__device__ __nv_bfloat16 g_Wqh[D_MODEL * D_MODEL];
__device__ __nv_bfloat16 g_Wql[D_MODEL * D_MODEL];
__device__ __nv_bfloat16 g_Wkh[D_MODEL * D_MODEL];
__device__ __nv_bfloat16 g_Wkl[D_MODEL * D_MODEL];
__device__ __nv_bfloat16 g_Qh[T_SEQ * D_MODEL];
__device__ __nv_bfloat16 g_Ql[T_SEQ * D_MODEL];
__device__ __nv_bfloat16 g_Kh[T_SEQ * D_MODEL];
__device__ __nv_bfloat16 g_Kl[T_SEQ * D_MODEL];

// ---------------- helpers ---------------------------------------------------
__device__ __forceinline__ uint32_t smem_u32(const void* p) {
    uint32_t a;
    asm("{ .reg .u64 t; cvta.to.shared.u64 t, %1; cvt.u32.u64 %0, t; }" : "=r"(a) : "l"(p));
    return a;
}
__device__ __forceinline__ void cp_async16(uint32_t s, const void* g) {
    asm volatile("cp.async.cg.shared.global [%0], [%1], 16;" :: "r"(s), "l"(g));
}
__device__ __forceinline__ void cp_commit() {
    asm volatile("cp.async.commit_group;" ::: "memory");
}
template <int N> __device__ __forceinline__ void cp_wait() {
    asm volatile("cp.async.wait_group %0;" :: "n"(N) : "memory");
}
__device__ __forceinline__ void ldsm4(uint32_t* r, uint32_t addr) {
    asm volatile("ldmatrix.sync.aligned.m8n8.x4.shared.b16 {%0,%1,%2,%3}, [%4];"
                 : "=r"(r[0]), "=r"(r[1]), "=r"(r[2]), "=r"(r[3]) : "r"(addr));
}
__device__ __forceinline__ void mma16816(float* c, const uint32_t* a, uint32_t b0, uint32_t b1) {
    asm volatile(
        "mma.sync.aligned.m16n8k16.row.col.f32.bf16.bf16.f32 "
        "{%0,%1,%2,%3}, {%4,%5,%6,%7}, {%8,%9}, {%0,%1,%2,%3};"
        : "+f"(c[0]), "+f"(c[1]), "+f"(c[2]), "+f"(c[3])
        : "r"(a[0]), "r"(a[1]), "r"(a[2]), "r"(a[3]), "r"(b0), "r"(b1));
}

// ---------------- fp32 -> bf16 hi/lo conversion ----------------------------
__global__ void convert_hilo(const float* __restrict__ s, __nv_bfloat16* __restrict__ hi,
                             __nv_bfloat16* __restrict__ lo, int n)
{
    int i = (blockIdx.x * blockDim.x + threadIdx.x) * 2;
    if (i < n) {
        float2 v = *(const float2*)(s + i);
        __nv_bfloat16 h0 = __float2bfloat16(v.x);
        __nv_bfloat16 h1 = __float2bfloat16(v.y);
        __nv_bfloat16 l0 = __float2bfloat16(v.x - __bfloat162float(h0));
        __nv_bfloat16 l1 = __float2bfloat16(v.y - __bfloat162float(h1));
        *(__nv_bfloat162*)(hi + i) = __halves2bfloat162(h0, h1);
        *(__nv_bfloat162*)(lo + i) = __halves2bfloat162(l0, l1);
    }
}

// ---------------- HMMA bf16x3 NT GEMM, 3-stage pipeline --------------------
// C[M,N] = alpha * A[M,K] * B[N,K]^T, A/B given as bf16 (hi,lo) pairs.
// Block tile 128x64, BK=32, 256 threads (8 warps, warp tile 32x32).
// blockIdx.z selects (B,C) pair (fused Q/K projections); z=0 uses B0/C0 outs.
// Dynamic smem ring: 3 stages x (A 16KB + B 8KB) = 72KB.
#define ASTG 16384
#define BSTG 8192
#define BOFF 49152
#define GEMM_SMEM 73728

__global__ __launch_bounds__(256, 2)
void gemm_mma_bf16x3(const __nv_bfloat16* __restrict__ Ah, const __nv_bfloat16* __restrict__ Al,
                     const __nv_bfloat16* __restrict__ B0h, const __nv_bfloat16* __restrict__ B0l,
                     const __nv_bfloat16* __restrict__ B1h, const __nv_bfloat16* __restrict__ B1l,
                     int K, float* __restrict__ Cf,
                     __nv_bfloat16* __restrict__ C0h, __nv_bfloat16* __restrict__ C0l,
                     __nv_bfloat16* __restrict__ C1h, __nv_bfloat16* __restrict__ C1l,
                     int ldc, float alpha, int lowerOnly)
{
    const int bj = blockIdx.x, bi = blockIdx.y, bz = blockIdx.z;
    if (lowerOnly && bj > 2 * bi + 1) return;

    const __nv_bfloat16* Bh = bz ? B1h : B0h;
    const __nv_bfloat16* Bl = bz ? B1l : B0l;
    __nv_bfloat16* Ch = bz ? C1h : C0h;
    __nv_bfloat16* Cl = bz ? C1l : C0l;

    extern __shared__ char smem[];
    const int tid = threadIdx.x;
    const uint32_t aBase = smem_u32(smem);
    const uint32_t bBase = aBase + BOFF;

    // ---- load-thread mapping (swizzle: chunk ^= (row>>1)&3) ----
    int aoff[2];
    size_t agoff[2];
    #pragma unroll
    for (int i = 0; i < 2; i++) {
        int idx = tid + i * 256;        // 0..511 -> 128 rows x 4 chunks
        int r = idx >> 2, cch = idx & 3;
        aoff[i] = (r * 4 + (cch ^ ((r >> 1) & 3))) * 16;
        agoff[i] = (size_t)r * K + cch * 8;
    }
    const int br = tid >> 2, bc = tid & 3;
    const int boff = (br * 4 + (bc ^ ((br >> 1) & 3))) * 16;
    const size_t bgoff = (size_t)br * K + bc * 8;

    const __nv_bfloat16* pAh = Ah + (size_t)(bi * 128) * K;
    const __nv_bfloat16* pAl = Al + (size_t)(bi * 128) * K;
    const __nv_bfloat16* pBh = Bh + (size_t)(bj * 64) * K;
    const __nv_bfloat16* pBl = Bl + (size_t)(bj * 64) * K;

    const int lane = tid & 31, wid = tid >> 5;
    const int wm = wid & 3, wn = wid >> 2;     // 4 x 2 warp grid
    const int lr = lane & 15, lg = lane >> 4;

    float c[2][4][4];
    #pragma unroll
    for (int i = 0; i < 2; i++)
        #pragma unroll
        for (int j = 0; j < 4; j++)
            #pragma unroll
            for (int q = 0; q < 4; q++) c[i][j][q] = 0.f;

    const int NIT = K >> 5;

    auto load_slot = [&](int it, int slot) {
        const int k0 = it << 5;
        const uint32_t aS = aBase + slot * ASTG;
        const uint32_t bS = bBase + slot * BSTG;
        #pragma unroll
        for (int i = 0; i < 2; i++) {
            cp_async16(aS + aoff[i],        pAh + k0 + agoff[i]);
            cp_async16(aS + 8192 + aoff[i], pAl + k0 + agoff[i]);
        }
        cp_async16(bS + boff,        pBh + k0 + bgoff);
        cp_async16(bS + 4096 + boff, pBl + k0 + bgoff);
    };

    load_slot(0, 0); cp_commit();
    load_slot(1, 1); cp_commit();

    int slot = 0;
    for (int it = 0; it < NIT; ++it) {
        cp_wait<1>();
        __syncthreads();
        if (it + 2 < NIT) load_slot(it + 2, (slot + 2) % 3);
        cp_commit();

        const uint32_t aHi = aBase + slot * ASTG;
        const uint32_t aLo = aHi + 8192;
        const uint32_t bHi = bBase + slot * BSTG;
        const uint32_t bLo = bHi + 4096;

        #pragma unroll
        for (int s = 0; s < 2; ++s) {
            uint32_t ah[2][4], al[2][4], bh[2][4], blr[2][4];
            #pragma unroll
            for (int mi = 0; mi < 2; mi++) {
                int r = wm * 32 + mi * 16 + lr;
                uint32_t off = r * 64 + (((2 * s + lg) ^ ((r >> 1) & 3)) * 16);
                ldsm4(ah[mi], aHi + off);
                ldsm4(al[mi], aLo + off);
            }
            #pragma unroll
            for (int ni = 0; ni < 2; ni++) {
                int r = wn * 32 + ni * 16 + lr;
                uint32_t off = r * 64 + (((2 * s + lg) ^ ((r >> 1) & 3)) * 16);
                ldsm4(bh[ni], bHi + off);
                ldsm4(blr[ni], bLo + off);
            }
            #pragma unroll
            for (int mi = 0; mi < 2; mi++)
                #pragma unroll
                for (int ni = 0; ni < 2; ni++)
                    #pragma unroll
                    for (int h = 0; h < 2; h++) {
                        float* cc = c[mi][ni * 2 + h];
                        mma16816(cc, ah[mi], bh[ni][h], bh[ni][h + 2]);
                        mma16816(cc, ah[mi], blr[ni][h], blr[ni][h + 2]);
                        mma16816(cc, al[mi], bh[ni][h], bh[ni][h + 2]);
                    }
        }
        slot = (slot + 1) % 3;
    }

    // ---- epilogue ----
    const int gq = lane >> 2, tig = lane & 3;
    #pragma unroll
    for (int mi = 0; mi < 2; mi++) {
        #pragma unroll
        for (int n8 = 0; n8 < 4; n8++) {
            int row0 = bi * 128 + wm * 32 + mi * 16 + gq;
            int col  = bj * 64 + wn * 32 + n8 * 8 + tig * 2;
            float* cc = c[mi][n8];
            if (Cf) {
                float2 v0, v1;
                v0.x = cc[0] * alpha; v0.y = cc[1] * alpha;
                v1.x = cc[2] * alpha; v1.y = cc[3] * alpha;
                *(float2*)(Cf + (size_t)row0 * ldc + col) = v0;
                *(float2*)(Cf + (size_t)(row0 + 8) * ldc + col) = v1;
            } else {
                #pragma unroll
                for (int hrow = 0; hrow < 2; hrow++) {
                    float v0 = cc[hrow * 2], v1 = cc[hrow * 2 + 1];
                    __nv_bfloat16 h0 = __float2bfloat16(v0);
                    __nv_bfloat16 h1 = __float2bfloat16(v1);
                    __nv_bfloat16 l0 = __float2bfloat16(v0 - __bfloat162float(h0));
                    __nv_bfloat16 l1 = __float2bfloat16(v1 - __bfloat162float(h1));
                    __nv_bfloat162 hh = __halves2bfloat162(h0, h1);
                    __nv_bfloat162 ll = __halves2bfloat162(l0, l1);
                    size_t o = (size_t)(row0 + hrow * 8) * ldc + col;
                    *(__nv_bfloat162*)(Ch + o) = hh;
                    *(__nv_bfloat162*)(Cl + o) = ll;
                }
            }
        }
    }
}

// ---------------- Threefry-2x32-20 (JAX partitionable path) ----------------
__device__ __forceinline__ uint32_t rotl32(uint32_t x, int r) {
    return (x << r) | (x >> (32 - r));
}
__device__ __forceinline__ uint32_t jax_random_bits(uint32_t idx) {
    const uint32_t ks0 = 0u;
    const uint32_t ks1 = 123u;
    const uint32_t ks2 = 0x1BD11BDAu ^ ks0 ^ ks1;
    uint32_t x0 = 0u + ks0;
    uint32_t x1 = idx + ks1;
#define TF_ROUND(r) { x0 += x1; x1 = rotl32(x1, (r)); x1 ^= x0; }
    TF_ROUND(13) TF_ROUND(15) TF_ROUND(26) TF_ROUND(6)
    x0 += ks1; x1 += ks2 + 1u;
    TF_ROUND(17) TF_ROUND(29) TF_ROUND(16) TF_ROUND(24)
    x0 += ks2; x1 += ks0 + 2u;
    TF_ROUND(13) TF_ROUND(15) TF_ROUND(26) TF_ROUND(6)
    x0 += ks0; x1 += ks1 + 3u;
    TF_ROUND(17) TF_ROUND(29) TF_ROUND(16) TF_ROUND(24)
    x0 += ks1; x1 += ks2 + 4u;
    TF_ROUND(13) TF_ROUND(15) TF_ROUND(26) TF_ROUND(6)
    x0 += ks2; x1 += ks0 + 5u;
#undef TF_ROUND
    return x0 ^ x1;
}

// ------------- Causal softmax + dropout (in place over d_out) --------------
__global__ __launch_bounds__(256)
void softmax_dropout_kernel(float* __restrict__ buf)
{
    int row = blockIdx.x;
    int tid = threadIdx.x;
    int len = row + 1;
    float* rp = buf + (size_t)row * T_SEQ;

    float v[16];
    float mx = -3.0e38f;
#pragma unroll
    for (int t = 0; t < 16; t++) {
        int j = tid + (t << 8);
        v[t] = (j < len) ? rp[j] : -3.0e38f;
        mx = fmaxf(mx, v[t]);
    }

    __shared__ float sred[8];
#pragma unroll
    for (int o = 16; o > 0; o >>= 1)
        mx = fmaxf(mx, __shfl_xor_sync(0xffffffffu, mx, o));
    if ((tid & 31) == 0) sred[tid >> 5] = mx;
    __syncthreads();
    mx = sred[0];
#pragma unroll
    for (int w = 1; w < 8; w++) mx = fmaxf(mx, sred[w]);

    float sum = 0.f;
#pragma unroll
    for (int t = 0; t < 16; t++) {
        int j = tid + (t << 8);
        if (j < len) { v[t] = __expf(v[t] - mx); sum += v[t]; }
    }
#pragma unroll
    for (int o = 16; o > 0; o >>= 1)
        sum += __shfl_xor_sync(0xffffffffu, sum, o);
    __syncthreads();
    if ((tid & 31) == 0) sred[tid >> 5] = sum;
    __syncthreads();
    sum = 0.f;
#pragma unroll
    for (int w = 0; w < 8; w++) sum += sred[w];

    float inv = 2.0f / sum;                  // includes /(1-p), p=0.5
    uint32_t base = (uint32_t)row * (uint32_t)T_SEQ + (uint32_t)tid;
#pragma unroll
    for (int t = 0; t < 16; t++) {
        int j = tid + (t << 8);
        float o = 0.f;
        if (j < len) {
            uint32_t bits = jax_random_bits(base + ((uint32_t)t << 8));
            if (!(bits & 0x80000000u)) o = v[t] * inv;
        }
        rp[j] = o;
    }
}

// ---------------------------------------------------------------------------
extern "C" void kernel_launch(void* const* d_in, const int* in_sizes, int n_in,
                              void* d_out, int out_size)
{
    const float* x  = (const float*)d_in[0];
    const float* Wq = (const float*)d_in[1];
    const float* Wk = (const float*)d_in[2];
    float* out = (float*)d_out;

    __nv_bfloat16 *xh, *xl, *wqh, *wql, *wkh, *wkl, *qh, *ql, *kh, *kl;
    cudaGetSymbolAddress((void**)&xh,  g_xh);
    cudaGetSymbolAddress((void**)&xl,  g_xl);
    cudaGetSymbolAddress((void**)&wqh, g_Wqh);
    cudaGetSymbolAddress((void**)&wql, g_Wql);
    cudaGetSymbolAddress((void**)&wkh, g_Wkh);
    cudaGetSymbolAddress((void**)&wkl, g_Wkl);
    cudaGetSymbolAddress((void**)&qh,  g_Qh);
    cudaGetSymbolAddress((void**)&ql,  g_Ql);
    cudaGetSymbolAddress((void**)&kh,  g_Kh);
    cudaGetSymbolAddress((void**)&kl,  g_Kl);

    cudaFuncSetAttribute(gemm_mma_bf16x3, cudaFuncAttributeMaxDynamicSharedMemorySize, GEMM_SMEM);

    int n1 = T_SEQ * D_MODEL, n2 = D_MODEL * D_MODEL;
    convert_hilo<<<(n1 / 2 + 255) / 256, 256>>>(x,  xh,  xl,  n1);
    convert_hilo<<<(n2 / 2 + 255) / 256, 256>>>(Wq, wqh, wql, n2);
    convert_hilo<<<(n2 / 2 + 255) / 256, 256>>>(Wk, wkh, wkl, n2);

    // Fused Q/K projections: z=0 -> Q = x@Wq^T, z=1 -> K = x@Wk^T (bf16 hi/lo outs)
    gemm_mma_bf16x3<<<dim3(D_MODEL / 64, T_SEQ / 128, 2), 256, GEMM_SMEM>>>(
        xh, xl, wqh, wql, wkh, wkl, D_MODEL, nullptr,
        qh, ql, kh, kl, D_MODEL, 1.0f, 0);
    // S = Q @ K^T / 32  (lower-triangular tiles only, fp32 to d_out)
    gemm_mma_bf16x3<<<dim3(T_SEQ / 64, T_SEQ / 128, 1), 256, GEMM_SMEM>>>(
        qh, ql, kh, kl, nullptr, nullptr, D_MODEL, out,
        nullptr, nullptr, nullptr, nullptr, T_SEQ, 0.03125f, 1);

    softmax_dropout_kernel<<<T_SEQ, 256>>>(out);
}

// round 5
// speedup vs baseline: 2.7077x; 1.0347x over previous
#include <cuda_runtime.h>
#include <cuda_bf16.h>
#include <cstdint>

#define T_SEQ 4096
#define D_MODEL 1024

// ---------------- scratch (__device__ globals; no allocs allowed) ----------
__device__ __nv_bfloat16 g_xh[T_SEQ * D_MODEL];
__device__ __nv_bfloat16 g_xl[T_SEQ * D_MODEL];
__device__ __nv_bfloat16 g_Wqh[D_MODEL * D_MODEL];
__device__ __nv_bfloat16 g_Wql[D_MODEL * D_MODEL];
__device__ __nv_bfloat16 g_Wkh[D_MODEL * D_MODEL];
__device__ __nv_bfloat16 g_Wkl[D_MODEL * D_MODEL];
__device__ __nv_bfloat16 g_Qh[T_SEQ * D_MODEL];
__device__ __nv_bfloat16 g_Ql[T_SEQ * D_MODEL];
__device__ __nv_bfloat16 g_Kh[T_SEQ * D_MODEL];
__device__ __nv_bfloat16 g_Kl[T_SEQ * D_MODEL];

// ---------------- helpers ---------------------------------------------------
__device__ __forceinline__ uint32_t smem_u32(const void* p) {
    uint32_t a;
    asm("{ .reg .u64 t; cvta.to.shared.u64 t, %1; cvt.u32.u64 %0, t; }" : "=r"(a) : "l"(p));
    return a;
}
__device__ __forceinline__ void cp_async16(uint32_t s, const void* g) {
    asm volatile("cp.async.cg.shared.global [%0], [%1], 16;" :: "r"(s), "l"(g));
}
__device__ __forceinline__ void cp_commit() {
    asm volatile("cp.async.commit_group;" ::: "memory");
}
template <int N> __device__ __forceinline__ void cp_wait() {
    asm volatile("cp.async.wait_group %0;" :: "n"(N) : "memory");
}
__device__ __forceinline__ void ldsm4(uint32_t* r, uint32_t addr) {
    asm volatile("ldmatrix.sync.aligned.m8n8.x4.shared.b16 {%0,%1,%2,%3}, [%4];"
                 : "=r"(r[0]), "=r"(r[1]), "=r"(r[2]), "=r"(r[3]) : "r"(addr));
}
__device__ __forceinline__ void mma16816(float* c, const uint32_t* a, uint32_t b0, uint32_t b1) {
    asm volatile(
        "mma.sync.aligned.m16n8k16.row.col.f32.bf16.bf16.f32 "
        "{%0,%1,%2,%3}, {%4,%5,%6,%7}, {%8,%9}, {%0,%1,%2,%3};"
        : "+f"(c[0]), "+f"(c[1]), "+f"(c[2]), "+f"(c[3])
        : "r"(a[0]), "r"(a[1]), "r"(a[2]), "r"(a[3]), "r"(b0), "r"(b1));
}

// ---------------- fp32 -> bf16 hi/lo conversion ----------------------------
__global__ void convert_hilo(const float* __restrict__ s, __nv_bfloat16* __restrict__ hi,
                             __nv_bfloat16* __restrict__ lo, int n)
{
    int i = (blockIdx.x * blockDim.x + threadIdx.x) * 2;
    if (i < n) {
        float2 v = *(const float2*)(s + i);
        __nv_bfloat16 h0 = __float2bfloat16(v.x);
        __nv_bfloat16 h1 = __float2bfloat16(v.y);
        __nv_bfloat16 l0 = __float2bfloat16(v.x - __bfloat162float(h0));
        __nv_bfloat16 l1 = __float2bfloat16(v.y - __bfloat162float(h1));
        *(__nv_bfloat162*)(hi + i) = __halves2bfloat162(h0, h1);
        *(__nv_bfloat162*)(lo + i) = __halves2bfloat162(l0, l1);
    }
}

// ---------------- HMMA bf16x3 NT GEMM, 3-stage pipeline --------------------
// C[M,N] = alpha * A[M,K] * B[N,K]^T, A/B given as bf16 (hi,lo) pairs.
// Block tile 128x64, BK=32, 256 threads (8 warps, warp tile 32x32).
// Mode lowerOnly=0: 3D grid, blockIdx.z selects (B,C) pair (fused Q/K proj).
// Mode lowerOnly=1: 1D grid of live lower-triangle tiles (bj <= 2*bi+1).
#define ASTG 16384
#define BSTG 8192
#define BOFF 49152
#define GEMM_SMEM 73728

__global__ __launch_bounds__(256, 3)
void gemm_mma_bf16x3(const __nv_bfloat16* __restrict__ Ah, const __nv_bfloat16* __restrict__ Al,
                     const __nv_bfloat16* __restrict__ B0h, const __nv_bfloat16* __restrict__ B0l,
                     const __nv_bfloat16* __restrict__ B1h, const __nv_bfloat16* __restrict__ B1l,
                     int K, float* __restrict__ Cf,
                     __nv_bfloat16* __restrict__ C0h, __nv_bfloat16* __restrict__ C0l,
                     __nv_bfloat16* __restrict__ C1h, __nv_bfloat16* __restrict__ C1l,
                     int ldc, float alpha, int lowerOnly)
{
    int bj, bi;
    const int bz = blockIdx.z;
    if (lowerOnly) {
        // decode t -> (bi, bj) with bi(bi+1) <= t < (bi+1)(bi+2), bj = t - bi(bi+1)
        int t = blockIdx.x;
        int b = (int)((sqrtf((float)(4 * t + 1)) - 1.0f) * 0.5f);
        while ((b + 1) * (b + 2) <= t) b++;
        while (b * (b + 1) > t) b--;
        bi = b;
        bj = t - b * (b + 1);
    } else {
        bj = blockIdx.x;
        bi = blockIdx.y;
    }

    const __nv_bfloat16* Bh = bz ? B1h : B0h;
    const __nv_bfloat16* Bl = bz ? B1l : B0l;
    __nv_bfloat16* Ch = bz ? C1h : C0h;
    __nv_bfloat16* Cl = bz ? C1l : C0l;

    extern __shared__ char smem[];
    const int tid = threadIdx.x;
    const uint32_t aBase = smem_u32(smem);
    const uint32_t bBase = aBase + BOFF;

    // ---- load-thread mapping (swizzle: chunk ^= (row>>1)&3) ----
    int aoff[2];
    size_t agoff[2];
    #pragma unroll
    for (int i = 0; i < 2; i++) {
        int idx = tid + i * 256;        // 0..511 -> 128 rows x 4 chunks
        int r = idx >> 2, cch = idx & 3;
        aoff[i] = (r * 4 + (cch ^ ((r >> 1) & 3))) * 16;
        agoff[i] = (size_t)r * K + cch * 8;
    }
    const int br = tid >> 2, bc = tid & 3;
    const int boff = (br * 4 + (bc ^ ((br >> 1) & 3))) * 16;
    const size_t bgoff = (size_t)br * K + bc * 8;

    const __nv_bfloat16* pAh = Ah + (size_t)(bi * 128) * K;
    const __nv_bfloat16* pAl = Al + (size_t)(bi * 128) * K;
    const __nv_bfloat16* pBh = Bh + (size_t)(bj * 64) * K;
    const __nv_bfloat16* pBl = Bl + (size_t)(bj * 64) * K;

    const int lane = tid & 31, wid = tid >> 5;
    const int wm = wid & 3, wn = wid >> 2;     // 4 x 2 warp grid
    const int lr = lane & 15, lg = lane >> 4;

    float c[2][4][4];
    #pragma unroll
    for (int i = 0; i < 2; i++)
        #pragma unroll
        for (int j = 0; j < 4; j++)
            #pragma unroll
            for (int q = 0; q < 4; q++) c[i][j][q] = 0.f;

    const int NIT = K >> 5;

    auto load_slot = [&](int it, int slot) {
        const int k0 = it << 5;
        const uint32_t aS = aBase + slot * ASTG;
        const uint32_t bS = bBase + slot * BSTG;
        #pragma unroll
        for (int i = 0; i < 2; i++) {
            cp_async16(aS + aoff[i],        pAh + k0 + agoff[i]);
            cp_async16(aS + 8192 + aoff[i], pAl + k0 + agoff[i]);
        }
        cp_async16(bS + boff,        pBh + k0 + bgoff);
        cp_async16(bS + 4096 + boff, pBl + k0 + bgoff);
    };

    load_slot(0, 0); cp_commit();
    load_slot(1, 1); cp_commit();

    int slot = 0;
    for (int it = 0; it < NIT; ++it) {
        cp_wait<1>();
        __syncthreads();
        if (it + 2 < NIT) load_slot(it + 2, (slot + 2) % 3);
        cp_commit();

        const uint32_t aHi = aBase + slot * ASTG;
        const uint32_t aLo = aHi + 8192;
        const uint32_t bHi = bBase + slot * BSTG;
        const uint32_t bLo = bHi + 4096;

        #pragma unroll
        for (int s = 0; s < 2; ++s) {
            uint32_t ah[2][4], al[2][4], bh[2][4], blr[2][4];
            #pragma unroll
            for (int mi = 0; mi < 2; mi++) {
                int r = wm * 32 + mi * 16 + lr;
                uint32_t off = r * 64 + (((2 * s + lg) ^ ((r >> 1) & 3)) * 16);
                ldsm4(ah[mi], aHi + off);
                ldsm4(al[mi], aLo + off);
            }
            #pragma unroll
            for (int ni = 0; ni < 2; ni++) {
                int r = wn * 32 + ni * 16 + lr;
                uint32_t off = r * 64 + (((2 * s + lg) ^ ((r >> 1) & 3)) * 16);
                ldsm4(bh[ni], bHi + off);
                ldsm4(blr[ni], bLo + off);
            }
            #pragma unroll
            for (int mi = 0; mi < 2; mi++)
                #pragma unroll
                for (int ni = 0; ni < 2; ni++)
                    #pragma unroll
                    for (int h = 0; h < 2; h++) {
                        float* cc = c[mi][ni * 2 + h];
                        mma16816(cc, ah[mi], bh[ni][h], bh[ni][h + 2]);
                        mma16816(cc, ah[mi], blr[ni][h], blr[ni][h + 2]);
                        mma16816(cc, al[mi], bh[ni][h], bh[ni][h + 2]);
                    }
        }
        slot = (slot + 1) % 3;
    }

    // ---- epilogue ----
    const int gq = lane >> 2, tig = lane & 3;
    #pragma unroll
    for (int mi = 0; mi < 2; mi++) {
        #pragma unroll
        for (int n8 = 0; n8 < 4; n8++) {
            int row0 = bi * 128 + wm * 32 + mi * 16 + gq;
            int col  = bj * 64 + wn * 32 + n8 * 8 + tig * 2;
            float* cc = c[mi][n8];
            if (Cf) {
                float2 v0, v1;
                v0.x = cc[0] * alpha; v0.y = cc[1] * alpha;
                v1.x = cc[2] * alpha; v1.y = cc[3] * alpha;
                *(float2*)(Cf + (size_t)row0 * ldc + col) = v0;
                *(float2*)(Cf + (size_t)(row0 + 8) * ldc + col) = v1;
            } else {
                #pragma unroll
                for (int hrow = 0; hrow < 2; hrow++) {
                    float v0 = cc[hrow * 2], v1 = cc[hrow * 2 + 1];
                    __nv_bfloat16 h0 = __float2bfloat16(v0);
                    __nv_bfloat16 h1 = __float2bfloat16(v1);
                    __nv_bfloat16 l0 = __float2bfloat16(v0 - __bfloat162float(h0));
                    __nv_bfloat16 l1 = __float2bfloat16(v1 - __bfloat162float(h1));
                    __nv_bfloat162 hh = __halves2bfloat162(h0, h1);
                    __nv_bfloat162 ll = __halves2bfloat162(l0, l1);
                    size_t o = (size_t)(row0 + hrow * 8) * ldc + col;
                    *(__nv_bfloat162*)(Ch + o) = hh;
                    *(__nv_bfloat162*)(Cl + o) = ll;
                }
            }
        }
    }
}

// ---------------- Threefry-2x32-20 (JAX partitionable path) ----------------
__device__ __forceinline__ uint32_t rotl32(uint32_t x, int r) {
    return (x << r) | (x >> (32 - r));
}
__device__ __forceinline__ uint32_t jax_random_bits(uint32_t idx) {
    const uint32_t ks0 = 0u;
    const uint32_t ks1 = 123u;
    const uint32_t ks2 = 0x1BD11BDAu ^ ks0 ^ ks1;
    uint32_t x0 = 0u + ks0;
    uint32_t x1 = idx + ks1;
#define TF_ROUND(r) { x0 += x1; x1 = rotl32(x1, (r)); x1 ^= x0; }
    TF_ROUND(13) TF_ROUND(15) TF_ROUND(26) TF_ROUND(6)
    x0 += ks1; x1 += ks2 + 1u;
    TF_ROUND(17) TF_ROUND(29) TF_ROUND(16) TF_ROUND(24)
    x0 += ks2; x1 += ks0 + 2u;
    TF_ROUND(13) TF_ROUND(15) TF_ROUND(26) TF_ROUND(6)
    x0 += ks0; x1 += ks1 + 3u;
    TF_ROUND(17) TF_ROUND(29) TF_ROUND(16) TF_ROUND(24)
    x0 += ks1; x1 += ks2 + 4u;
    TF_ROUND(13) TF_ROUND(15) TF_ROUND(26) TF_ROUND(6)
    x0 += ks2; x1 += ks0 + 5u;
#undef TF_ROUND
    return x0 ^ x1;
}

// ------------- Causal softmax + dropout (in place over d_out) --------------
__global__ __launch_bounds__(256)
void softmax_dropout_kernel(float* __restrict__ buf)
{
    int row = blockIdx.x;
    int tid = threadIdx.x;
    int len = row + 1;
    float* rp = buf + (size_t)row * T_SEQ;

    float v[16];
    float mx = -3.0e38f;
#pragma unroll
    for (int t = 0; t < 16; t++) {
        int j = tid + (t << 8);
        v[t] = (j < len) ? rp[j] : -3.0e38f;
        mx = fmaxf(mx, v[t]);
    }

    __shared__ float sred[8];
#pragma unroll
    for (int o = 16; o > 0; o >>= 1)
        mx = fmaxf(mx, __shfl_xor_sync(0xffffffffu, mx, o));
    if ((tid & 31) == 0) sred[tid >> 5] = mx;
    __syncthreads();
    mx = sred[0];
#pragma unroll
    for (int w = 1; w < 8; w++) mx = fmaxf(mx, sred[w]);

    float sum = 0.f;
#pragma unroll
    for (int t = 0; t < 16; t++) {
        int j = tid + (t << 8);
        if (j < len) { v[t] = __expf(v[t] - mx); sum += v[t]; }
    }
#pragma unroll
    for (int o = 16; o > 0; o >>= 1)
        sum += __shfl_xor_sync(0xffffffffu, sum, o);
    __syncthreads();
    if ((tid & 31) == 0) sred[tid >> 5] = sum;
    __syncthreads();
    sum = 0.f;
#pragma unroll
    for (int w = 0; w < 8; w++) sum += sred[w];

    float inv = 2.0f / sum;                  // includes /(1-p), p=0.5
    uint32_t base = (uint32_t)row * (uint32_t)T_SEQ + (uint32_t)tid;
#pragma unroll
    for (int t = 0; t < 16; t++) {
        int j = tid + (t << 8);
        float o = 0.f;
        if (j < len) {
            uint32_t bits = jax_random_bits(base + ((uint32_t)t << 8));
            if (!(bits & 0x80000000u)) o = v[t] * inv;
        }
        rp[j] = o;
    }
}

// ---------------------------------------------------------------------------
extern "C" void kernel_launch(void* const* d_in, const int* in_sizes, int n_in,
                              void* d_out, int out_size)
{
    const float* x  = (const float*)d_in[0];
    const float* Wq = (const float*)d_in[1];
    const float* Wk = (const float*)d_in[2];
    float* out = (float*)d_out;

    __nv_bfloat16 *xh, *xl, *wqh, *wql, *wkh, *wkl, *qh, *ql, *kh, *kl;
    cudaGetSymbolAddress((void**)&xh,  g_xh);
    cudaGetSymbolAddress((void**)&xl,  g_xl);
    cudaGetSymbolAddress((void**)&wqh, g_Wqh);
    cudaGetSymbolAddress((void**)&wql, g_Wql);
    cudaGetSymbolAddress((void**)&wkh, g_Wkh);
    cudaGetSymbolAddress((void**)&wkl, g_Wkl);
    cudaGetSymbolAddress((void**)&qh,  g_Qh);
    cudaGetSymbolAddress((void**)&ql,  g_Ql);
    cudaGetSymbolAddress((void**)&kh,  g_Kh);
    cudaGetSymbolAddress((void**)&kl,  g_Kl);

    cudaFuncSetAttribute(gemm_mma_bf16x3, cudaFuncAttributeMaxDynamicSharedMemorySize, GEMM_SMEM);

    int n1 = T_SEQ * D_MODEL, n2 = D_MODEL * D_MODEL;
    convert_hilo<<<(n1 / 2 + 255) / 256, 256>>>(x,  xh,  xl,  n1);
    convert_hilo<<<(n2 / 2 + 255) / 256, 256>>>(Wq, wqh, wql, n2);
    convert_hilo<<<(n2 / 2 + 255) / 256, 256>>>(Wk, wkh, wkl, n2);

    // Fused Q/K projections: z=0 -> Q = x@Wq^T, z=1 -> K = x@Wk^T (bf16 hi/lo outs)
    gemm_mma_bf16x3<<<dim3(D_MODEL / 64, T_SEQ / 128, 2), 256, GEMM_SMEM>>>(
        xh, xl, wqh, wql, wkh, wkl, D_MODEL, nullptr,
        qh, ql, kh, kl, D_MODEL, 1.0f, 0);
    // S = Q @ K^T / 32 : 1D grid of live lower-triangle tiles only.
    // #tiles = sum_{bi=0}^{31} (2*bi+2) = 1056
    gemm_mma_bf16x3<<<dim3(1056, 1, 1), 256, GEMM_SMEM>>>(
        qh, ql, kh, kl, nullptr, nullptr, D_MODEL, out,
        nullptr, nullptr, nullptr, nullptr, T_SEQ, 0.03125f, 1);

    softmax_dropout_kernel<<<T_SEQ, 256>>>(out);
}